// round 15
// baseline (speedup 1.0000x reference)
#include <cuda_runtime.h>
#include <math.h>

#define NN 8192
#define PAD 128            // padded-CSR slots per node; max in-degree ~66 << 128
#define CB  256            // chain blocks (bids 0..CB-1), all wave-1 resident
#define THREADS 256

// Scratch (allocation-free rule: device globals).
// g_cnt/g_bar/g_exit are zero at context init and reset in-kernel after use,
// so every launch (and every graph replay) starts from a clean state.
__device__ int   g_cnt   [NN];
__device__ int   g_colpad[NN * PAD];   // 4MB
__device__ float g_dinv  [NN];
__device__ float g_W1s   [NN * 16];    // dinv[n] * W1[n,:]
__device__ float g_h2s   [NN * 8];     // dinv[n] * h2[n,:]
__device__ float g_x2    [NN * 8];
__device__ int   g_bar;
__device__ int   g_exit;

// Barrier among the CB chain blocks only (all wave-1 resident by construction).
__device__ __forceinline__ void chain_barrier(int target) {
    __threadfence();
    __syncthreads();
    if (threadIdx.x == 0) {
        atomicAdd(&g_bar, 1);
        while (atomicAdd(&g_bar, 0) < target) __nanosleep(64);
    }
    __syncthreads();
    __threadfence();
}

// FUSED: 8192 blocks, one output row each (zero-fill at the write floor).
// Blocks 0..CB-1 additionally run the GCN chain first; its ~20us hides under
// the ~52us write stream of the other 7936 blocks.
__global__ void __launch_bounds__(THREADS)
k_fused(float* __restrict__ out,
        const int* __restrict__ ei, int E,
        const float* __restrict__ W1, const float* __restrict__ b1,
        const float* __restrict__ W2, const float* __restrict__ b2)
{
    const int bid = blockIdx.x;
    const int tid = threadIdx.x;

    if (bid < CB) {
        const int t0 = bid * THREADS + tid;
        const int T  = CB * THREADS;           // 65536 chain threads
        const int lane = tid & 31;

        // ---- stage 0: padded-CSR fill (cnt doubles as in-degree) ----
        for (int e = t0; e < E; e += T) {
            int s = ei[e];
            int d = ei[E + e];
            int pos = atomicAdd(&g_cnt[d], 1);
            g_colpad[d * PAD + pos] = s;
        }
        chain_barrier(CB * 1);

        // ---- stage 1: dinv + scaled W1 ----
        for (int i = t0; i < NN * 16; i += T) {
            int n = i >> 4;
            int f = i & 15;
            float dn = rsqrtf((float)g_cnt[n] + 1.0f);
            if (f == 0) g_dinv[n] = dn;
            g_W1s[i] = dn * W1[i];
        }
        chain_barrier(CB * 2);

        // ---- stage 2: conv1 (warp/node, 16 feats x 2 halves) ----
        {
            int gwarp = t0 >> 5;               // 0..2047
            int f    = lane & 15;
            int half = lane >> 4;
            for (int n = gwarp; n < NN; n += (T >> 5)) {   // uniform trips
                float dn  = g_dinv[n];
                int   deg = g_cnt[n];
                const int* col = &g_colpad[n * PAD];
                float acc = 0.0f;
                for (int e = half; e < deg; e += 2)
                    acc += g_W1s[(size_t)col[e] * 16 + f];
                acc += __shfl_xor_sync(0xffffffffu, acc, 16);
                float xf = fmaxf(dn * (acc + g_W1s[(size_t)n * 16 + f]) + b1[f],
                                 0.0f);
                int j = f & 7;
                float h = 0.0f;
#pragma unroll
                for (int k = 0; k < 16; k++) {
                    float xk = __shfl_sync(0xffffffffu, xf, k);
                    h += xk * W2[k * 8 + j];
                }
                if (lane < 8) g_h2s[(size_t)n * 8 + j] = dn * h;
            }
        }
        chain_barrier(CB * 3);

        // ---- stage 3: conv2 (warp/node, 8 feats x 4 quarters) + cnt reset ----
        {
            int gwarp = t0 >> 5;
            int j = lane & 7;
            int q = lane >> 3;
            for (int n = gwarp; n < NN; n += (T >> 5)) {
                float dn  = g_dinv[n];
                int   deg = g_cnt[n];
                const int* col = &g_colpad[n * PAD];
                float acc = 0.0f;
                for (int e = q; e < deg; e += 4)
                    acc += g_h2s[(size_t)col[e] * 8 + j];
                acc += __shfl_xor_sync(0xffffffffu, acc, 8);
                acc += __shfl_xor_sync(0xffffffffu, acc, 16);
                float v = dn * (acc + g_h2s[(size_t)n * 8 + j]) + b2[j];
                if (lane < 8) g_x2[(size_t)n * 8 + j] = fmaxf(v, 0.0f);
                if (lane == 31) g_cnt[n] = 0;  // reset for next replay
            }
        }

        // ---- exit protocol: reset barrier state for the next replay ----
        __threadfence();
        __syncthreads();
        if (tid == 0) {
            atomicAdd(&g_exit, 1);
            if (bid == 0) {
                while (atomicAdd(&g_exit, 0) < CB) __nanosleep(64);
                g_bar = 0;
                g_exit = 0;
                __threadfence();
            }
        }
    }

    // ---- every block: zero its output row (write-floor streaming stores) ----
    float4* rp = (float4*)(out + (size_t)bid * NN);
    float4 z = make_float4(0.0f, 0.0f, 0.0f, 0.0f);
#pragma unroll
    for (int k = 0; k < 8; k++)                // 2048 float4 per row
        __stwt(&rp[tid + k * THREADS], z);
}

// scatter 1.0f at every directed edge (ordered after zeros by kernel boundary)
__global__ void k_ones(const int* __restrict__ ei, int E,
                       float* __restrict__ out) {
    int e = blockIdx.x * blockDim.x + threadIdx.x;
    if (e >= E) return;
    int s = ei[e];
    int d = ei[E + e];
    out[(size_t)s * NN + d] = 1.0f;
}

// orientation head: out[u,v] = sigmoid(ef @ Wfc + bfc); out[v,u] = 1 - it
__global__ void k_edgeout(const int* __restrict__ ue,
                          const float* __restrict__ Wfc,
                          const float* __restrict__ bfc,
                          float* __restrict__ out, int U) {
    int i = blockIdx.x * blockDim.x + threadIdx.x;
    if (i >= U) return;
    int u = ue[2 * i];
    int v = ue[2 * i + 1];
    float s = bfc[0];
#pragma unroll
    for (int f = 0; f < 8; f++) {
        s += g_x2[(size_t)u * 8 + f] * Wfc[f];
        s += g_x2[(size_t)v * 8 + f] * Wfc[8 + f];
    }
    float o = 1.0f / (1.0f + expf(-s));
    out[(size_t)u * NN + v] = o;
    out[(size_t)v * NN + u] = 1.0f - o;
}

extern "C" void kernel_launch(void* const* d_in, const int* in_sizes, int n_in,
                              void* d_out, int out_size) {
    const float* W1  = (const float*)d_in[1];
    const float* b1  = (const float*)d_in[2];
    const float* W2  = (const float*)d_in[3];
    const float* b2  = (const float*)d_in[4];
    const float* Wfc = (const float*)d_in[5];
    const float* bfc = (const float*)d_in[6];
    const int*   ei  = (const int*)d_in[7];
    const int*   ue  = (const int*)d_in[8];

    int E = in_sizes[7] / 2;
    int U = in_sizes[8] / 2;

    const int B = 256;

    k_fused  <<<NN, THREADS>>>((float*)d_out, ei, E, W1, b1, W2, b2);
    k_ones   <<<(E + B - 1) / B, B>>>(ei, E, (float*)d_out);
    k_edgeout<<<(U + B - 1) / B, B>>>(ue, Wfc, bfc, (float*)d_out, U);
}

// round 16
// speedup vs baseline: 1.1030x; 1.1030x over previous
#include <cuda_runtime.h>
#include <math.h>

#define NN 8192
#define PAD 128            // padded-CSR slots per node; max in-degree ~66 << 128

// Scratch (allocation-free rule: device globals).
// g_cnt is zero at context init and reset by k_conv2 after its last read,
// so every launch (and every graph replay) starts from a clean state.
__device__ int   g_cnt    [NN];
__device__ int4  g_colpad4[NN * PAD / 4];   // 4MB, int4-aligned for batch loads
__device__ float g_dinv   [NN];
__device__ float g_W1s    [NN * 16];        // dinv[n] * W1[n,:]
__device__ float g_h2s    [NN * 8];         // dinv[n] * h2[n,:]
__device__ float g_x2     [NN * 8];

// ---------------------------------------------------------------------------
// 1. padded-CSR fill, 2 independent edges per thread (ILP for the 318-cyc
//    atomic latency). cnt doubles as the in-degree afterwards.
__global__ void k_fill(const int* __restrict__ ei, int E) {
    int t = blockIdx.x * blockDim.x + threadIdx.x;
    int e = t * 2;
    if (e >= E) return;
    int* col = (int*)g_colpad4;
    int s0 = ei[e];
    int d0 = ei[E + e];
    int p0 = atomicAdd(&g_cnt[d0], 1);
    if (e + 1 < E) {
        int s1 = ei[e + 1];
        int d1 = ei[E + e + 1];
        int p1 = atomicAdd(&g_cnt[d1], 1);
        col[d1 * PAD + p1] = s1;
    }
    col[d0 * PAD + p0] = s0;
}

// 2. prep: dinv = rsqrt(deg+1); W1s[n,f] = dinv[n]*W1[n,f]
__global__ void k_prep(const float* __restrict__ W1) {
    int tid = blockIdx.x * blockDim.x + threadIdx.x;
    if (tid >= NN * 16) return;
    int n = tid >> 4;
    int f = tid & 15;
    float dn = rsqrtf((float)g_cnt[n] + 1.0f);
    if (f == 0) g_dinv[n] = dn;
    g_W1s[tid] = dn * W1[tid];
}

// 3. conv1: warp per node, 16 feats x 2 halves. Each half batch-loads 8
//    indices via two int4 (broadcast), then 8 independent predicated gathers
//    into 4 accumulators (MLP ~8 instead of dependent col->gather chain).
__global__ void k_conv1(const float* __restrict__ b1,
                        const float* __restrict__ W2) {
    int tid  = blockIdx.x * blockDim.x + threadIdx.x;
    int n    = tid >> 5;
    if (n >= NN) return;
    int lane = threadIdx.x & 31;
    int f    = lane & 15;
    int half = lane >> 4;                // 0 or 1: alternating 8-edge batches

    float dn  = g_dinv[n];
    int   deg = g_cnt[n];
    const int4* col4 = &g_colpad4[n * (PAD / 4)];

    float a0 = 0.0f, a1 = 0.0f, a2 = 0.0f, a3 = 0.0f;
    for (int b = half; b * 8 < deg; b += 2) {
        int4 c0 = col4[2 * b];
        int4 c1 = col4[2 * b + 1];       // may read past deg: own scratch, ok
        int  e0 = b * 8;
        if (e0 + 0 < deg) a0 += g_W1s[(size_t)c0.x * 16 + f];
        if (e0 + 1 < deg) a1 += g_W1s[(size_t)c0.y * 16 + f];
        if (e0 + 2 < deg) a2 += g_W1s[(size_t)c0.z * 16 + f];
        if (e0 + 3 < deg) a3 += g_W1s[(size_t)c0.w * 16 + f];
        if (e0 + 4 < deg) a0 += g_W1s[(size_t)c1.x * 16 + f];
        if (e0 + 5 < deg) a1 += g_W1s[(size_t)c1.y * 16 + f];
        if (e0 + 6 < deg) a2 += g_W1s[(size_t)c1.z * 16 + f];
        if (e0 + 7 < deg) a3 += g_W1s[(size_t)c1.w * 16 + f];
    }
    float acc = (a0 + a1) + (a2 + a3);
    acc += __shfl_xor_sync(0xffffffffu, acc, 16);          // combine halves
    float xf = fmaxf(dn * (acc + g_W1s[(size_t)n * 16 + f]) + b1[f], 0.0f);

    // h2[n,j] = sum_k xf(k) * W2[k,j]; store scaled by dinv[n]
    int j = f & 7;
    float h = 0.0f;
#pragma unroll
    for (int k = 0; k < 16; k++) {
        float xk = __shfl_sync(0xffffffffu, xf, k);        // lane k holds feat k
        h += xk * W2[k * 8 + j];
    }
    if (lane < 8) g_h2s[(size_t)n * 8 + j] = dn * h;
}

// 4. conv2 (+ fused ones-scatter): warp per node, 8 feats x 4 quarter-batches,
//    same int4 batching. Threads with tid < E also write 1.0f at their
//    directed edge (independent store; ordered after the memset by the
//    stream). Resets g_cnt[n] = 0 after the last read (replay-clean).
__global__ void k_conv2(const float* __restrict__ b2,
                        const int* __restrict__ ei, int E,
                        float* __restrict__ out) {
    int tid  = blockIdx.x * blockDim.x + threadIdx.x;

    if (tid < E) {                        // fused k_ones
        int s = ei[tid];
        int d = ei[E + tid];
        out[(size_t)s * NN + d] = 1.0f;
    }

    int n = tid >> 5;
    if (n >= NN) return;
    int lane = threadIdx.x & 31;
    int j    = lane & 7;
    int q    = lane >> 3;                 // 0..3: quarter-batches

    float dn  = g_dinv[n];
    int   deg = g_cnt[n];
    const int4* col4 = &g_colpad4[n * (PAD / 4)];

    float a0 = 0.0f, a1 = 0.0f;
    for (int b = q; b * 8 < deg; b += 4) {
        int4 c0 = col4[2 * b];
        int4 c1 = col4[2 * b + 1];
        int  e0 = b * 8;
        if (e0 + 0 < deg) a0 += g_h2s[(size_t)c0.x * 8 + j];
        if (e0 + 1 < deg) a1 += g_h2s[(size_t)c0.y * 8 + j];
        if (e0 + 2 < deg) a0 += g_h2s[(size_t)c0.z * 8 + j];
        if (e0 + 3 < deg) a1 += g_h2s[(size_t)c0.w * 8 + j];
        if (e0 + 4 < deg) a0 += g_h2s[(size_t)c1.x * 8 + j];
        if (e0 + 5 < deg) a1 += g_h2s[(size_t)c1.y * 8 + j];
        if (e0 + 6 < deg) a0 += g_h2s[(size_t)c1.z * 8 + j];
        if (e0 + 7 < deg) a1 += g_h2s[(size_t)c1.w * 8 + j];
    }
    float acc = a0 + a1;
    acc += __shfl_xor_sync(0xffffffffu, acc, 8);
    acc += __shfl_xor_sync(0xffffffffu, acc, 16);
    float v = dn * (acc + g_h2s[(size_t)n * 8 + j]) + b2[j];
    if (lane < 8) g_x2[(size_t)n * 8 + j] = fmaxf(v, 0.0f);
    if (lane == 31) g_cnt[n] = 0;         // reset for next replay
}

// 5. orientation head: out[u,v] = sigmoid(ef @ Wfc + bfc); out[v,u] = 1 - it
__global__ void k_edgeout(const int* __restrict__ ue,
                          const float* __restrict__ Wfc,
                          const float* __restrict__ bfc,
                          float* __restrict__ out, int U) {
    int i = blockIdx.x * blockDim.x + threadIdx.x;
    if (i >= U) return;
    int u = ue[2 * i];
    int v = ue[2 * i + 1];
    float s = bfc[0];
#pragma unroll
    for (int f = 0; f < 8; f++) {
        s += g_x2[(size_t)u * 8 + f] * Wfc[f];
        s += g_x2[(size_t)v * 8 + f] * Wfc[8 + f];
    }
    float o = 1.0f / (1.0f + expf(-s));
    out[(size_t)u * NN + v] = o;
    out[(size_t)v * NN + u] = 1.0f - o;
}

extern "C" void kernel_launch(void* const* d_in, const int* in_sizes, int n_in,
                              void* d_out, int out_size) {
    const float* W1  = (const float*)d_in[1];
    const float* b1  = (const float*)d_in[2];
    const float* W2  = (const float*)d_in[3];
    const float* b2  = (const float*)d_in[4];
    const float* Wfc = (const float*)d_in[5];
    const float* bfc = (const float*)d_in[6];
    const int*   ei  = (const int*)d_in[7];
    const int*   ue  = (const int*)d_in[8];

    int E = in_sizes[7] / 2;
    int U = in_sizes[8] / 2;

    const int B = 256;

    // Serial single-stream pipeline (overlap proven unprofitable 5x).
    cudaMemsetAsync(d_out, 0, (size_t)out_size * sizeof(float), 0);
    k_fill <<<(E / 2 + B) / B, B>>>(ei, E);
    k_prep <<<(NN * 16 + B - 1) / B, B>>>(W1);
    k_conv1<<<(NN * 32 + B - 1) / B, B>>>(b1, W2);
    int cover = NN * 32 > E ? NN * 32 : E;          // conv2 grid also covers E
    k_conv2<<<(cover + B - 1) / B, B>>>(b2, ei, E, (float*)d_out);
    k_edgeout<<<(U + B - 1) / B, B>>>(ue, Wfc, bfc, (float*)d_out, U);
}

// round 17
// speedup vs baseline: 1.1315x; 1.0259x over previous
#include <cuda_runtime.h>
#include <math.h>

#define NN 8192
#define PAD  128           // in/out CSR slots per node; max degree ~70 << 128
#define PADU 64            // undirected-incidence slots; max ~45 << 64

// Scratch (allocation-free rule: device globals).
// All cnt arrays are zero at context init and reset in-kernel after last use,
// so every launch (and every graph replay) starts from a clean state.
__device__ int   g_cnt    [NN];             // in-degree  (dst-CSR)
__device__ int   g_cnt2   [NN];             // out-degree (src-CSR)
__device__ int   g_cnt3   [NN];             // undirected incidence count
__device__ int4  g_colin4 [NN * PAD / 4];   // in-CSR, int4 for batched loads
__device__ int   g_colout [NN * PAD];       // out-CSR: dst per src
__device__ int   g_colund [NN * PADU];      // partner | (flag<<31)
__device__ float g_dinv   [NN];
__device__ float g_W1s    [NN * 16];        // dinv[n] * W1[n,:]
__device__ float g_h2s    [NN * 8];         // dinv[n] * h2[n,:]
__device__ float g_x2     [NN * 8];

// ---------------------------------------------------------------------------
// 1. one-pass fill of all three CSRs
__global__ void k_fill(const int* __restrict__ ei, int E,
                       const int* __restrict__ ue, int U) {
    int t = blockIdx.x * blockDim.x + threadIdx.x;
    if (t < E) {
        int s = ei[t];
        int d = ei[E + t];
        int p1 = atomicAdd(&g_cnt[d], 1);
        ((int*)g_colin4)[d * PAD + p1] = s;
        int p2 = atomicAdd(&g_cnt2[s], 1);
        g_colout[s * PAD + p2] = d;
    } else if (t < E + U) {
        int i = t - E;
        int u = ue[2 * i];
        int v = ue[2 * i + 1];
        int q1 = atomicAdd(&g_cnt3[u], 1);
        g_colund[u * PADU + q1] = v;                 // flag 0: row is u
        int q2 = atomicAdd(&g_cnt3[v], 1);
        g_colund[v * PADU + q2] = u | (int)0x80000000; // flag 1: row is v
    }
}

// 2. prep: dinv = rsqrt(deg+1); W1s[n,f] = dinv[n]*W1[n,f]
__global__ void k_prep(const float* __restrict__ W1) {
    int tid = blockIdx.x * blockDim.x + threadIdx.x;
    if (tid >= NN * 16) return;
    int n = tid >> 4;
    int f = tid & 15;
    float dn = rsqrtf((float)g_cnt[n] + 1.0f);
    if (f == 0) g_dinv[n] = dn;
    g_W1s[tid] = dn * W1[tid];
}

// 3. conv1: warp per node, 16 feats x 2 halves; int4 index batching (MLP~8).
__global__ void k_conv1(const float* __restrict__ b1,
                        const float* __restrict__ W2) {
    int tid  = blockIdx.x * blockDim.x + threadIdx.x;
    int n    = tid >> 5;
    if (n >= NN) return;
    int lane = threadIdx.x & 31;
    int f    = lane & 15;
    int half = lane >> 4;                // 0 or 1: alternating 8-edge batches

    float dn  = g_dinv[n];
    int   deg = g_cnt[n];
    const int4* col4 = &g_colin4[n * (PAD / 4)];

    float a0 = 0.0f, a1 = 0.0f, a2 = 0.0f, a3 = 0.0f;
    for (int b = half; b * 8 < deg; b += 2) {
        int4 c0 = col4[2 * b];
        int4 c1 = col4[2 * b + 1];       // own scratch; stale slots predicated
        int  e0 = b * 8;
        if (e0 + 0 < deg) a0 += g_W1s[(size_t)c0.x * 16 + f];
        if (e0 + 1 < deg) a1 += g_W1s[(size_t)c0.y * 16 + f];
        if (e0 + 2 < deg) a2 += g_W1s[(size_t)c0.z * 16 + f];
        if (e0 + 3 < deg) a3 += g_W1s[(size_t)c0.w * 16 + f];
        if (e0 + 4 < deg) a0 += g_W1s[(size_t)c1.x * 16 + f];
        if (e0 + 5 < deg) a1 += g_W1s[(size_t)c1.y * 16 + f];
        if (e0 + 6 < deg) a2 += g_W1s[(size_t)c1.z * 16 + f];
        if (e0 + 7 < deg) a3 += g_W1s[(size_t)c1.w * 16 + f];
    }
    float acc = (a0 + a1) + (a2 + a3);
    acc += __shfl_xor_sync(0xffffffffu, acc, 16);          // combine halves
    float xf = fmaxf(dn * (acc + g_W1s[(size_t)n * 16 + f]) + b1[f], 0.0f);

    // h2[n,j] = sum_k xf(k) * W2[k,j]; store scaled by dinv[n]
    int j = f & 7;
    float h = 0.0f;
#pragma unroll
    for (int k = 0; k < 16; k++) {
        float xk = __shfl_sync(0xffffffffu, xf, k);        // lane k holds feat k
        h += xk * W2[k * 8 + j];
    }
    if (lane < 8) g_h2s[(size_t)n * 8 + j] = dn * h;
}

// 4. conv2: warp per node, 8 feats x 4 quarter-batches; NO d_out stores.
//    Resets g_cnt[n] = 0 after the last read (replay-clean).
__global__ void k_conv2(const float* __restrict__ b2) {
    int tid  = blockIdx.x * blockDim.x + threadIdx.x;
    int n    = tid >> 5;
    if (n >= NN) return;
    int lane = threadIdx.x & 31;
    int j    = lane & 7;
    int q    = lane >> 3;                 // 0..3: quarter-batches

    float dn  = g_dinv[n];
    int   deg = g_cnt[n];
    const int4* col4 = &g_colin4[n * (PAD / 4)];

    float a0 = 0.0f, a1 = 0.0f;
    for (int b = q; b * 8 < deg; b += 4) {
        int4 c0 = col4[2 * b];
        int4 c1 = col4[2 * b + 1];
        int  e0 = b * 8;
        if (e0 + 0 < deg) a0 += g_h2s[(size_t)c0.x * 8 + j];
        if (e0 + 1 < deg) a1 += g_h2s[(size_t)c0.y * 8 + j];
        if (e0 + 2 < deg) a0 += g_h2s[(size_t)c0.z * 8 + j];
        if (e0 + 3 < deg) a1 += g_h2s[(size_t)c0.w * 8 + j];
        if (e0 + 4 < deg) a0 += g_h2s[(size_t)c1.x * 8 + j];
        if (e0 + 5 < deg) a1 += g_h2s[(size_t)c1.y * 8 + j];
        if (e0 + 6 < deg) a0 += g_h2s[(size_t)c1.z * 8 + j];
        if (e0 + 7 < deg) a1 += g_h2s[(size_t)c1.w * 8 + j];
    }
    float acc = a0 + a1;
    acc += __shfl_xor_sync(0xffffffffu, acc, 8);
    acc += __shfl_xor_sync(0xffffffffu, acc, 16);
    float v = dn * (acc + g_h2s[(size_t)n * 8 + j]) + b2[j];
    if (lane < 8) g_x2[(size_t)n * 8 + j] = fmaxf(v, 0.0f);
    if (lane == 31) g_cnt[n] = 0;         // reset for next replay
}

// 5. rowfill: one block per output row, at the write floor.
//    zeros (streaming stores) -> ones at out-edges -> orientation values.
//    All d_out traffic lives here, hidden under the 52us stream.
__global__ void __launch_bounds__(256)
k_rowfill(float* __restrict__ out,
          const float* __restrict__ Wfc, const float* __restrict__ bfc) {
    int r = blockIdx.x;
    int t = threadIdx.x;
    float4* rp = (float4*)(out + (size_t)r * NN);

    float4 z = make_float4(0.0f, 0.0f, 0.0f, 0.0f);
#pragma unroll
    for (int k = 0; k < 8; k++)                    // 2048 float4 per row
        __stwt(&rp[t + k * 256], z);
    __syncthreads();                               // zeros before ones

    int odeg = g_cnt2[r];
    if (t < odeg) out[(size_t)r * NN + g_colout[r * PAD + t]] = 1.0f;
    __syncthreads();                               // ones before orientation

    int udeg = g_cnt3[r];
    if (t < udeg) {
        int packed = g_colund[r * PADU + t];
        int p      = packed & 0x7fffffff;
        int flag   = (int)((unsigned)packed >> 31);
        // ef = [x2[u], x2[v]] with u = (flag ? p : r), v = (flag ? r : p);
        // identical operand order on both endpoints -> bit-identical o.
        const float* xa = &g_x2[(size_t)(flag ? p : r) * 8];
        const float* xb = &g_x2[(size_t)(flag ? r : p) * 8];
        float s = bfc[0];
#pragma unroll
        for (int f = 0; f < 8; f++)
            s += xa[f] * Wfc[f] + xb[f] * Wfc[8 + f];
        float o = 1.0f / (1.0f + expf(-s));
        out[(size_t)r * NN + p] = flag ? (1.0f - o) : o;
    }
    if (t == 0) { g_cnt2[r] = 0; g_cnt3[r] = 0; }  // reset for next replay
}

extern "C" void kernel_launch(void* const* d_in, const int* in_sizes, int n_in,
                              void* d_out, int out_size) {
    const float* W1  = (const float*)d_in[1];
    const float* b1  = (const float*)d_in[2];
    const float* W2  = (const float*)d_in[3];
    const float* b2  = (const float*)d_in[4];
    const float* Wfc = (const float*)d_in[5];
    const float* bfc = (const float*)d_in[6];
    const int*   ei  = (const int*)d_in[7];
    const int*   ue  = (const int*)d_in[8];

    int E = in_sizes[7] / 2;
    int U = in_sizes[8] / 2;

    const int B = 256;

    // Serial single-stream pipeline; all d_out writes in the floor kernel.
    k_fill   <<<(E + U + B - 1) / B, B>>>(ei, E, ue, U);
    k_prep   <<<(NN * 16 + B - 1) / B, B>>>(W1);
    k_conv1  <<<(NN * 32 + B - 1) / B, B>>>(b1, W2);
    k_conv2  <<<(NN * 32 + B - 1) / B, B>>>(b2);
    k_rowfill<<<NN, B>>>((float*)d_out, Wfc, bfc);
}